// round 2
// baseline (speedup 1.0000x reference)
#include <cuda_runtime.h>
#include <math.h>

#define FULL 0xffffffffu
#define SCALE 0.08838834764831845f
#define B 32
#define H 16
#define D 128
#define BS 16
#define MAX_BLOCKS 64
#define NWARP 8

__global__ __launch_bounds__(256) void paged_attn_kernel(
    const float* __restrict__ q,      // [B,H,D]
    const float* __restrict__ knew,   // [B,H,D]
    const float* __restrict__ vnew,   // [B,H,D]
    const float* __restrict__ kc,     // [NB,H,D/X=16,BS=16,X=8]
    const float* __restrict__ vc,     // [NB,H,BS=16,D=128]
    const int*   __restrict__ bt,     // [B,MAX_BLOCKS]
    const int*   __restrict__ cl,     // [B]
    float*       __restrict__ out)    // [B,H*D]
{
    const int bh = blockIdx.x;          // b*H + h
    const int b  = bh >> 4;
    const int h  = bh & 15;
    const int tid  = threadIdx.x;
    const int w    = tid >> 5;
    const int lane = tid & 31;
    const int t    = lane & 15;         // token within block
    const int h2   = lane >> 4;         // dim-half

    __shared__ float qs[D];
    __shared__ float sm_m[NWARP];
    __shared__ float sm_l[NWARP];
    __shared__ float sm_o[NWARP][D];

    // stage q into shared (32 lanes x float4 = 128 floats)
    if (tid < 32) {
        ((float4*)qs)[tid] = ((const float4*)(q + (size_t)bh * D))[tid];
    }
    __syncthreads();

    const int ctx  = cl[b];
    const int nb   = (ctx + BS - 1) >> 4;
    const int last = ctx - 1;

    float m = -INFINITY;
    float l = 0.f;
    float4 o = make_float4(0.f, 0.f, 0.f, 0.f);

    const float4* qs4   = (const float4*)qs;
    const float4* knew4 = (const float4*)(knew + (size_t)bh * D);
    const float4* vnew4 = (const float4*)(vnew + (size_t)bh * D);

    for (int j = w; j < nb; j += NWARP) {
        const int blk = bt[b * MAX_BLOCKS + j];
        const float* kb = kc + (size_t)(blk * H + h) * 2048;
        const float* vb = vc + (size_t)(blk * H + h) * 2048;

        const int pos   = (j << 4) + t;
        const bool isnew = (pos == last);

        // ---- score: dot(q, k_pos) split over h2 halves ----
        float s = 0.f;
        #pragma unroll
        for (int c = 0; c < 8; c++) {
            const int dx = c * 2 + h2;            // dim-chunk index (0..15)
            float4 ka, kb4;
            if (isnew) {
                ka  = knew4[dx * 2];
                kb4 = knew4[dx * 2 + 1];
            } else {
                const float* kptr = kb + dx * 128 + t * 8;
                ka  = *(const float4*)(kptr);
                kb4 = *(const float4*)(kptr + 4);
            }
            const float4 qa = qs4[dx * 2];
            const float4 qb = qs4[dx * 2 + 1];
            s += ka.x*qa.x + ka.y*qa.y + ka.z*qa.z + ka.w*qa.w;
            s += kb4.x*qb.x + kb4.y*qb.y + kb4.z*qb.z + kb4.w*qb.w;
        }
        s += __shfl_xor_sync(FULL, s, 16);        // combine the two halves
        s *= SCALE;
        if (pos >= ctx) s = -INFINITY;

        // ---- block max across 16 tokens ----
        float bm = s;
        #pragma unroll
        for (int dlt = 8; dlt >= 1; dlt >>= 1)
            bm = fmaxf(bm, __shfl_xor_sync(FULL, bm, dlt));

        const float mn = fmaxf(m, bm);
        const float scale_old = __expf(m - mn);   // first iter: exp(-inf - finite) = 0
        const float p = __expf(s - mn);           // masked: exp(-inf) = 0

        float ps = p;
        #pragma unroll
        for (int dlt = 8; dlt >= 1; dlt >>= 1)
            ps += __shfl_xor_sync(FULL, ps, dlt);

        l = l * scale_old + ps;
        m = mn;
        o.x *= scale_old; o.y *= scale_old; o.z *= scale_old; o.w *= scale_old;

        // ---- accumulate V: lane owns dims [lane*4, lane*4+4) ----
        #pragma unroll 4
        for (int tt = 0; tt < BS; tt++) {
            const float pt = __shfl_sync(FULL, p, tt);   // uniform across warp
            if (pt != 0.f) {
                const int posv = (j << 4) + tt;
                const float4* vp = (posv == last) ? vnew4
                                                  : (const float4*)(vb + tt * 128);
                const float4 vv = vp[lane];
                o.x += pt * vv.x; o.y += pt * vv.y;
                o.z += pt * vv.z; o.w += pt * vv.w;
            }
        }
    }

    // ---- merge 8 per-warp partials (log-sum-exp) ----
    if (lane == 0) { sm_m[w] = m; sm_l[w] = l; }
    ((float4*)sm_o[w])[lane] = o;
    __syncthreads();

    if (tid < D) {
        float M = -INFINITY;
        #pragma unroll
        for (int ww = 0; ww < NWARP; ww++) M = fmaxf(M, sm_m[ww]);
        float L = 0.f, val = 0.f;
        #pragma unroll
        for (int ww = 0; ww < NWARP; ww++) {
            const float sc = __expf(sm_m[ww] - M);
            L   += sm_l[ww] * sc;
            val += sm_o[ww][tid] * sc;
        }
        out[(size_t)bh * D + tid] = val / L;
    }
}

extern "C" void kernel_launch(void* const* d_in, const int* in_sizes, int n_in,
                              void* d_out, int out_size) {
    const float* q    = (const float*)d_in[0];
    const float* knew = (const float*)d_in[1];
    const float* vnew = (const float*)d_in[2];
    const float* kc   = (const float*)d_in[3];
    const float* vc   = (const float*)d_in[4];
    const int*   bt   = (const int*)d_in[5];
    const int*   cl   = (const int*)d_in[6];
    // d_in[7] = slot_mapping (unused: the new token is injected at pos ctx-1 directly)
    float* out = (float*)d_out;

    paged_attn_kernel<<<B * H, 256>>>(q, knew, vnew, kc, vc, bt, cl, out);
}

// round 6
// speedup vs baseline: 2.0505x; 2.0505x over previous
#include <cuda_runtime.h>
#include <math.h>

#define FULL 0xffffffffu
#define SCALE 0.08838834764831845f
#define B 32
#define H 16
#define D 128
#define BS 16
#define MAX_BLOCKS 64
#define SPLIT 4
#define NWARP 4                 // warps per CTA
#define NPART (SPLIT * NWARP)   // partials per (b,h) = 16

// scratch for split-KV partials (device globals: allowed, no allocation)
__device__ float g_m[B * H * NPART];
__device__ float g_l[B * H * NPART];
__device__ float g_o[B * H * NPART * D];

__global__ __launch_bounds__(128) void paged_attn_split_kernel(
    const float* __restrict__ q,      // [B,H,D]
    const float* __restrict__ knew,   // [B,H,D]
    const float* __restrict__ vnew,   // [B,H,D]
    const float* __restrict__ kc,     // [NB,H,16,16,8]
    const float* __restrict__ vc,     // [NB,H,16,128]
    const int*   __restrict__ bt,     // [B,MAX_BLOCKS]
    const int*   __restrict__ cl)     // [B]
{
    const int cta = blockIdx.x;         // bh*SPLIT + s
    const int bh  = cta >> 2;
    const int s   = cta & (SPLIT - 1);
    const int b   = bh >> 4;
    const int h   = bh & 15;
    const int tid  = threadIdx.x;
    const int w    = tid >> 5;
    const int lane = tid & 31;
    const int t    = lane & 15;         // token within block
    const int h2   = lane >> 4;         // dim-half

    __shared__ float qs[D];
    if (tid < 32)
        ((float4*)qs)[tid] = ((const float4*)(q + (size_t)bh * D))[tid];
    __syncthreads();

    const int ctx   = cl[b];
    const int nb    = (ctx + BS - 1) >> 4;
    const int last  = ctx - 1;
    const int chunk = (nb + SPLIT - 1) >> 2;
    const int j0    = s * chunk;
    const int j1    = min(j0 + chunk, nb);

    float m = -INFINITY;
    float l = 0.f;
    float4 o = make_float4(0.f, 0.f, 0.f, 0.f);

    const float4* qs4   = (const float4*)qs;
    const float4* knew4 = (const float4*)(knew + (size_t)bh * D);
    const float4* vnew4 = (const float4*)(vnew + (size_t)bh * D);

    for (int j = j0 + w; j < j1; j += NWARP) {
        const int blk = bt[b * MAX_BLOCKS + j];
        const float* kb = kc + (size_t)(blk * H + h) * 2048;
        const float* vb = vc + (size_t)(blk * H + h) * 2048;

        const int pos   = (j << 4) + t;
        const bool isnew = (pos == last);

        // ---- score: dot(q, k_pos), halves split over h2, 16 loads in flight ----
        float sc = 0.f;
        #pragma unroll
        for (int c = 0; c < 8; c++) {
            const int dx = c * 2 + h2;
            float4 ka, kb4;
            if (isnew) {
                ka  = knew4[dx * 2];
                kb4 = knew4[dx * 2 + 1];
            } else {
                const float* kptr = kb + dx * 128 + t * 8;
                ka  = *(const float4*)(kptr);
                kb4 = *(const float4*)(kptr + 4);
            }
            const float4 qa = qs4[dx * 2];
            const float4 qb = qs4[dx * 2 + 1];
            sc += ka.x*qa.x + ka.y*qa.y + ka.z*qa.z + ka.w*qa.w;
            sc += kb4.x*qb.x + kb4.y*qb.y + kb4.z*qb.z + kb4.w*qb.w;
        }
        sc += __shfl_xor_sync(FULL, sc, 16);
        sc *= SCALE;
        if (pos >= ctx) sc = -INFINITY;

        // ---- block max over 16 tokens ----
        float bm = sc;
        #pragma unroll
        for (int dlt = 8; dlt >= 1; dlt >>= 1)
            bm = fmaxf(bm, __shfl_xor_sync(FULL, bm, dlt));

        const float mn = fmaxf(m, bm);
        const float scale_old = __expf(m - mn);
        const float p = __expf(sc - mn);       // masked: exp(-inf)=0

        float ps = p;
        #pragma unroll
        for (int dlt = 8; dlt >= 1; dlt >>= 1)
            ps += __shfl_xor_sync(FULL, ps, dlt);

        l = l * scale_old + ps;
        m = mn;
        o.x *= scale_old; o.y *= scale_old; o.z *= scale_old; o.w *= scale_old;

        // ---- V accumulate: unconditional loads, 8 in flight per batch ----
        #pragma unroll
        for (int tt0 = 0; tt0 < BS; tt0 += 8) {
            float4 vv[8];
            #pragma unroll
            for (int u = 0; u < 8; u++) {
                const int posv = (j << 4) + tt0 + u;
                const float4* vp = (posv == last) ? vnew4
                                 : (const float4*)(vb + (tt0 + u) * 128);
                vv[u] = vp[lane];
            }
            #pragma unroll
            for (int u = 0; u < 8; u++) {
                const float pt = __shfl_sync(FULL, p, tt0 + u);
                o.x += pt * vv[u].x; o.y += pt * vv[u].y;
                o.z += pt * vv[u].z; o.w += pt * vv[u].w;
            }
        }
    }

    // ---- write this warp's partial ----
    const int pid = (bh << 4) + (s << 2) + w;
    if (lane == 0) { g_m[pid] = m; g_l[pid] = l; }
    ((float4*)(g_o + (size_t)pid * D))[lane] = o;
}

__global__ __launch_bounds__(128) void merge_kernel(float* __restrict__ out)
{
    const int bh = blockIdx.x;
    const int d  = threadIdx.x;
    const int base = bh << 4;

    float M = -INFINITY;
    #pragma unroll
    for (int i = 0; i < NPART; i++) M = fmaxf(M, g_m[base + i]);

    float L = 0.f, val = 0.f;
    #pragma unroll
    for (int i = 0; i < NPART; i++) {
        const float sc = __expf(g_m[base + i] - M);
        L   += g_l[base + i] * sc;
        val += g_o[(size_t)(base + i) * D + d] * sc;
    }
    out[(size_t)bh * D + d] = val / L;
}

extern "C" void kernel_launch(void* const* d_in, const int* in_sizes, int n_in,
                              void* d_out, int out_size) {
    const float* q    = (const float*)d_in[0];
    const float* knew = (const float*)d_in[1];
    const float* vnew = (const float*)d_in[2];
    const float* kc   = (const float*)d_in[3];
    const float* vc   = (const float*)d_in[4];
    const int*   bt   = (const int*)d_in[5];
    const int*   cl   = (const int*)d_in[6];
    float* out = (float*)d_out;

    paged_attn_split_kernel<<<B * H * SPLIT, 128>>>(q, knew, vnew, kc, vc, bt, cl);
    merge_kernel<<<B * H, 128>>>(out);
}

// round 7
// speedup vs baseline: 2.1183x; 1.0331x over previous
#include <cuda_runtime.h>
#include <math.h>

#define FULL 0xffffffffu
#define SCALE 0.08838834764831845f
#define B 32
#define H 16
#define D 128
#define BS 16
#define MAX_BLOCKS 64
#define SPLIT 4
#define NWARP 4                 // warps per CTA

// scratch for split-KV partials (one per CTA) + completion counters
__device__ float g_m[B * H * SPLIT];
__device__ float g_l[B * H * SPLIT];
__device__ float g_o[B * H * SPLIT * D];
__device__ int   g_cnt[B * H];          // zero-init; reset to 0 by merge -> replay-safe

__global__ __launch_bounds__(128) void paged_attn_fused_kernel(
    const float* __restrict__ q,      // [B,H,D]
    const float* __restrict__ knew,   // [B,H,D]
    const float* __restrict__ vnew,   // [B,H,D]
    const float* __restrict__ kc,     // [NB,H,16,16,8]
    const float* __restrict__ vc,     // [NB,H,16,128]
    const int*   __restrict__ bt,     // [B,MAX_BLOCKS]
    const int*   __restrict__ cl,     // [B]
    float*       __restrict__ out)    // [B,H*D]
{
    const int cta = blockIdx.x;         // bh*SPLIT + s
    const int bh  = cta >> 2;
    const int s   = cta & (SPLIT - 1);
    const int b   = bh >> 4;
    const int h   = bh & 15;
    const int tid  = threadIdx.x;
    const int w    = tid >> 5;
    const int lane = tid & 31;
    const int t    = lane & 15;         // token within block
    const int h2   = lane >> 4;         // dim-half

    __shared__ float qs[D];
    __shared__ float sm_m[NWARP];
    __shared__ float sm_l[NWARP];
    __shared__ float sm_o[NWARP][D];
    __shared__ int   sm_last;

    if (tid < 32)
        ((float4*)qs)[tid] = ((const float4*)(q + (size_t)bh * D))[tid];
    __syncthreads();

    const int ctx   = cl[b];
    const int nb    = (ctx + BS - 1) >> 4;
    const int last  = ctx - 1;
    const int chunk = (nb + SPLIT - 1) >> 2;
    const int j0    = s * chunk;
    const int j1    = min(j0 + chunk, nb);

    float m = -INFINITY;
    float l = 0.f;
    float4 o = make_float4(0.f, 0.f, 0.f, 0.f);

    const float4* qs4   = (const float4*)qs;
    const float4* knew4 = (const float4*)(knew + (size_t)bh * D);
    const float4* vnew4 = (const float4*)(vnew + (size_t)bh * D);

    for (int j = j0 + w; j < j1; j += NWARP) {
        const int blk = bt[b * MAX_BLOCKS + j];
        const float* kb = kc + (size_t)(blk * H + h) * 2048;
        const float* vb = vc + (size_t)(blk * H + h) * 2048;

        const int pos   = (j << 4) + t;
        const bool isnew = (pos == last);

        // ---- score: dot(q, k_pos), halves split over h2, 16 loads in flight ----
        float sc = 0.f;
        #pragma unroll
        for (int c = 0; c < 8; c++) {
            const int dx = c * 2 + h2;
            float4 ka, kb4;
            if (isnew) {
                ka  = knew4[dx * 2];
                kb4 = knew4[dx * 2 + 1];
            } else {
                const float* kptr = kb + dx * 128 + t * 8;
                ka  = *(const float4*)(kptr);
                kb4 = *(const float4*)(kptr + 4);
            }
            const float4 qa = qs4[dx * 2];
            const float4 qb = qs4[dx * 2 + 1];
            sc += ka.x*qa.x + ka.y*qa.y + ka.z*qa.z + ka.w*qa.w;
            sc += kb4.x*qb.x + kb4.y*qb.y + kb4.z*qb.z + kb4.w*qb.w;
        }
        sc += __shfl_xor_sync(FULL, sc, 16);
        sc *= SCALE;
        if (pos >= ctx) sc = -INFINITY;

        // ---- block max over 16 tokens ----
        float bm = sc;
        #pragma unroll
        for (int dlt = 8; dlt >= 1; dlt >>= 1)
            bm = fmaxf(bm, __shfl_xor_sync(FULL, bm, dlt));

        const float mn = fmaxf(m, bm);
        const float scale_old = __expf(m - mn);
        const float p = __expf(sc - mn);       // masked: exp(-inf)=0

        float ps = p;
        #pragma unroll
        for (int dlt = 8; dlt >= 1; dlt >>= 1)
            ps += __shfl_xor_sync(FULL, ps, dlt);

        l = l * scale_old + ps;
        m = mn;
        o.x *= scale_old; o.y *= scale_old; o.z *= scale_old; o.w *= scale_old;

        // ---- V accumulate: unconditional loads, 8 in flight per batch ----
        #pragma unroll
        for (int tt0 = 0; tt0 < BS; tt0 += 8) {
            float4 vv[8];
            #pragma unroll
            for (int u = 0; u < 8; u++) {
                const int posv = (j << 4) + tt0 + u;
                const float4* vp = (posv == last) ? vnew4
                                 : (const float4*)(vb + (tt0 + u) * 128);
                vv[u] = vp[lane];
            }
            #pragma unroll
            for (int u = 0; u < 8; u++) {
                const float pt = __shfl_sync(FULL, p, tt0 + u);
                o.x += pt * vv[u].x; o.y += pt * vv[u].y;
                o.z += pt * vv[u].z; o.w += pt * vv[u].w;
            }
        }
    }

    // ---- intra-CTA merge of 4 warp partials (smem) ----
    if (lane == 0) { sm_m[w] = m; sm_l[w] = l; }
    ((float4*)sm_o[w])[lane] = o;
    __syncthreads();

    float Mc = -INFINITY;
    #pragma unroll
    for (int ww = 0; ww < NWARP; ww++) Mc = fmaxf(Mc, sm_m[ww]);
    float Lc = 0.f, vc_acc = 0.f;
    #pragma unroll
    for (int ww = 0; ww < NWARP; ww++) {
        const float scw = __expf(sm_m[ww] - Mc);
        Lc     += sm_l[ww] * scw;
        vc_acc += sm_o[ww][tid] * scw;
    }

    // ---- publish CTA partial, then last-arriving CTA merges ----
    const int pid = (bh << 2) + s;
    g_o[(size_t)pid * D + tid] = vc_acc;
    if (tid == 0) { g_m[pid] = Mc; g_l[pid] = Lc; }
    __threadfence();
    __syncthreads();
    if (tid == 0)
        sm_last = (atomicAdd(&g_cnt[bh], 1) == SPLIT - 1);
    __syncthreads();

    if (sm_last) {
        const int base = bh << 2;
        float M = -INFINITY;
        #pragma unroll
        for (int i = 0; i < SPLIT; i++) M = fmaxf(M, g_m[base + i]);
        float L = 0.f, val = 0.f;
        #pragma unroll
        for (int i = 0; i < SPLIT; i++) {
            const float sci = __expf(g_m[base + i] - M);
            L   += g_l[base + i] * sci;
            val += g_o[(size_t)(base + i) * D + tid] * sci;
        }
        out[(size_t)bh * D + tid] = val / L;
        if (tid == 0) g_cnt[bh] = 0;      // reset for next launch / graph replay
    }
}

extern "C" void kernel_launch(void* const* d_in, const int* in_sizes, int n_in,
                              void* d_out, int out_size) {
    const float* q    = (const float*)d_in[0];
    const float* knew = (const float*)d_in[1];
    const float* vnew = (const float*)d_in[2];
    const float* kc   = (const float*)d_in[3];
    const float* vc   = (const float*)d_in[4];
    const int*   bt   = (const int*)d_in[5];
    const int*   cl   = (const int*)d_in[6];
    float* out = (float*)d_out;

    paged_attn_fused_kernel<<<B * H * SPLIT, 128>>>(q, knew, vnew, kc, vc, bt, cl, out);
}